// round 13
// baseline (speedup 1.0000x reference)
#include <cuda_runtime.h>
#include <cuda_bf16.h>
#include <cstdint>

#define NB    4
#define NSEQ  4096
#define DIM   512
#define BQ    64
#define BK    64
#define NKT   (NSEQ/BK)
#define NTHR  256
#define THRESH 70.0f

// fp8(e4m3) copy of X (no cudaMalloc allowed -> device global scratch)
__device__ uint8_t g_X8[(size_t)NB*NSEQ*DIM];

// dynamic smem: 3-buffer fp8 tile ring (rows 512B, swizzled 16B chunks) + candidates
#define SM_K(i)  ((i)*32768)
#define SM_CAND  98304                  // float2[64][16] = 8KB
#define SMEM_BYTES (98304 + 8192)       // 106496

// ---------------- PTX helpers (plain-sm_103 legal) ----------------
__device__ __forceinline__ uint32_t smem_u32(const void* p) {
    uint32_t a;
    asm("{ .reg .u64 t; cvta.to.shared.u64 t, %1; cvt.u32.u64 %0, t; }" : "=r"(a) : "l"(p));
    return a;
}
#define CP16(dst, src) \
    asm volatile("cp.async.cg.shared.global [%0], [%1], 16;" \
        :: "r"((uint32_t)(dst)), "l"((unsigned long long)__cvta_generic_to_global((const void*)(src))) : "memory")
#define CP_COMMIT()  asm volatile("cp.async.commit_group;" ::: "memory")
#define CP_WAIT(n)   asm volatile("cp.async.wait_group %0;" :: "n"(n) : "memory")

__device__ __forceinline__ void ldsm4(uint32_t* r, uint32_t a) {
    asm volatile("ldmatrix.sync.aligned.m8n8.x4.shared.b16 {%0,%1,%2,%3}, [%4];"
        : "=r"(r[0]), "=r"(r[1]), "=r"(r[2]), "=r"(r[3]) : "r"(a));
}
// fp8 e4m3 MMA: D(16x8 f32) += A(16x32 e4m3) * B(32x8 e4m3)
__device__ __forceinline__ void mma_fp8(float* c, const uint32_t* a, const uint32_t* b) {
    asm volatile("mma.sync.aligned.m16n8k32.row.col.f32.e4m3.e4m3.f32 "
        "{%0,%1,%2,%3}, {%4,%5,%6,%7}, {%8,%9}, {%0,%1,%2,%3};"
        : "+f"(c[0]), "+f"(c[1]), "+f"(c[2]), "+f"(c[3])
        : "r"(a[0]), "r"(a[1]), "r"(a[2]), "r"(a[3]), "r"(b[0]), "r"(b[1]));
}
// rows are 512B = 32 x 16B chunks; XOR low-3 chunk bits with row%8 (conflict-free ldsm)
__device__ __forceinline__ int swz(int c, int r) { return c ^ (r & 7); }

__device__ __forceinline__ void ins2(float v, int idx, float& t1, int& i1, float& t2, int& i2) {
    if (v > t2) {
        if (v > t1) { t2 = t1; i2 = i1; t1 = v; i1 = idx; }
        else        { t2 = v;  i2 = idx; }
    }
}

// load a 64x512 fp8 tile (rows 512B) into swizzled smem via cp.async (2048 chunks)
__device__ __forceinline__ void load_tile(uint32_t sbase, const uint8_t* src, int tid) {
#pragma unroll
    for (int i = 0; i < 8; ++i) {
        int c   = tid + i * NTHR;
        int row = c >> 5, ch = c & 31;
        CP16(sbase + row * 512 + swz(ch, row) * 16, src + (size_t)row * DIM + ch * 16);
    }
    CP_COMMIT();
}

// f32 -> e4m3 (satfinite); pack pairs via cvt.e4m3x2
__device__ __forceinline__ uint32_t cvt4_e4m3(float4 v) {
    uint16_t lo, hi;
    asm("cvt.rn.satfinite.e4m3x2.f32 %0, %2, %1;" : "=h"(lo) : "f"(v.x), "f"(v.y));
    asm("cvt.rn.satfinite.e4m3x2.f32 %0, %2, %1;" : "=h"(hi) : "f"(v.z), "f"(v.w));
    return (uint32_t)lo | ((uint32_t)hi << 16);
}

extern "C" __global__ void cvt_kernel(const float* __restrict__ X) {
    size_t i = (size_t)blockIdx.x * 256 + threadIdx.x;   // one float4 -> 4 bytes
    ((uint32_t*)g_X8)[i] = cvt4_e4m3(((const float4*)X)[i]);
}

// 256 threads = 8 warps = 4 wq x 2 wk. Warp tile: 16 q-rows x 32 keys x 512 dims (fp8).
// Q fragments live in registers (64 regs); K streams through a 3-buffer ring.
extern "C" __global__ void __launch_bounds__(NTHR, 2)
attn_mma_kernel(const float* __restrict__ X, float* __restrict__ Y)
{
    extern __shared__ char smem[];
    const uint32_t sb = smem_u32(smem);
    const int tid  = threadIdx.x, lane = tid & 31, w = tid >> 5;
    const int wq = w & 3, wk = w >> 2;
    const int b  = blockIdx.x >> 6;
    const int q0 = (blockIdx.x & 63) * BQ;
    const uint8_t* Xb = g_X8 + (size_t)b * NSEQ * DIM;

    // prologue: stage Q into buf2, K0 into buf0, K1 into buf1
    load_tile(sb + SM_K(2), Xb + (size_t)q0 * DIM, tid);
    load_tile(sb + SM_K(0), Xb, tid);
    load_tile(sb + SM_K(1), Xb + (size_t)BK * DIM, tid);

    // per-lane ldmatrix coordinates (identical double-pump structure to bf16-k16)
    const int aco  = (lane >> 4);                 // k-half chunk for a2/a3
    const int bco  = (lane >> 3) & 1;             // k-half chunk for b1
    const int arow = wq * 16 + (lane & 7) + ((lane >> 3) & 1) * 8;
    const int brow0 = wk * 32 + (lane & 7) + ((lane >> 4) & 1) * 8;
    const int brow1 = brow0 + 16;

    // extract Q fragments into registers (16 k-steps x 4 regs = 64 regs)
    CP_WAIT(2);            // Q group retired (K0,K1 may be in flight)
    __syncthreads();
    uint32_t A[16][4];
    {
        const uint32_t qbase = sb + SM_K(2) + arow * 512;
#pragma unroll
        for (int ks = 0; ks < 16; ++ks)
            ldsm4(A[ks], qbase + swz(ks * 2 + aco, arow) * 16);
    }
    __syncthreads();       // buf2 free for the ring

    float t1[2] = {-1e30f, -1e30f}, t2[2] = {-1e30f, -1e30f};
    int   i1[2] = {0, 0},           i2[2] = {0, 0};

    int bufk = 0;          // buf index of tile kt; ring 0,1,2,0,...
    for (int kt = 0; kt < NKT; ++kt) {
        if (kt + 1 < NKT) { CP_WAIT(1); } else { CP_WAIT(0); }  // tile kt landed
        __syncthreads();                                         // visible; compute(kt-1) done by all
        if (kt + 2 < NKT) {
            int ibuf = bufk + 2; if (ibuf >= 3) ibuf -= 3;
            load_tile(sb + SM_K(ibuf), Xb + (size_t)(kt + 2) * BK * DIM, tid);
        }

        const uint32_t kbase = sb + SM_K(bufk);
        const uint32_t kb0 = kbase + brow0 * 512;
        const uint32_t kb1 = kbase + brow1 * 512;
        float acc[4][4];
#pragma unroll
        for (int nt = 0; nt < 4; ++nt)
#pragma unroll
            for (int e = 0; e < 4; ++e) acc[nt][e] = 0.0f;

#pragma unroll
        for (int ks = 0; ks < 16; ++ks) {         // 16 steps x 32 dims
            uint32_t B0[4], B1[4];
            ldsm4(B0, kb0 + swz(ks * 2 + bco, brow0) * 16);
            ldsm4(B1, kb1 + swz(ks * 2 + bco, brow1) * 16);
            mma_fp8(acc[0], A[ks], B0);       // keys +0..7
            mma_fp8(acc[1], A[ks], B0 + 2);   // keys +8..15
            mma_fp8(acc[2], A[ks], B1);       // keys +16..23
            mma_fp8(acc[3], A[ks], B1 + 2);   // keys +24..31
        }

        // survivor tracking (thread rows: wq*16 + lane/4, +8; cols: wk*32 + nt*8 + (lane&3)*2)
        float tmax = acc[0][0];
#pragma unroll
        for (int nt = 0; nt < 4; ++nt)
#pragma unroll
            for (int e = 0; e < 4; ++e) tmax = fmaxf(tmax, acc[nt][e]);
        if (tmax > fminf(t2[0], t2[1])) {
            const int cb = kt * BK + wk * 32 + (lane & 3) * 2;
#pragma unroll
            for (int nt = 0; nt < 4; ++nt) {
                ins2(acc[nt][0], cb + nt * 8,     t1[0], i1[0], t2[0], i2[0]);
                ins2(acc[nt][1], cb + nt * 8 + 1, t1[0], i1[0], t2[0], i2[0]);
                ins2(acc[nt][2], cb + nt * 8,     t1[1], i1[1], t2[1], i2[1]);
                ins2(acc[nt][3], cb + nt * 8 + 1, t1[1], i1[1], t2[1], i2[1]);
            }
        }

        if (++bufk == 3) bufk = 0;
    }

    // publish per-thread candidates: cand[row][16] float2 (score, idx-bits)
    float2* cand = (float2*)(smem + SM_CAND);
#pragma unroll
    for (int s = 0; s < 2; ++s) {
        const int row  = wq * 16 + s * 8 + (lane >> 2);
        const int slot = (wk * 4 + (lane & 3)) * 2;
        cand[row * 16 + slot]     = make_float2(t1[s], __int_as_float(i1[s]));
        cand[row * 16 + slot + 1] = make_float2(t2[s], __int_as_float(i2[s]));
    }
    __syncthreads();

    // epilogue: one thread per query row; exact fp32 softmax over survivors.
    if (tid < BQ) {
        const int q = q0 + tid;
        float mx = -1e30f;
#pragma unroll
        for (int s = 0; s < 16; ++s) mx = fmaxf(mx, cand[tid * 16 + s].x);

        int idxs[16]; int n2 = 0;
#pragma unroll
        for (int s = 0; s < 16; ++s) {
            float2 c = cand[tid * 16 + s];
            if (c.x > mx - THRESH) idxs[n2++] = __float_as_int(c.y);
        }

        const float* Xf = X + (size_t)b * NSEQ * DIM;
        const float* xq = Xf + (size_t)q * DIM;
        float se[16], mex = -1e30f;
        for (int i = 0; i < n2; ++i) {
            const float* xj = Xf + (size_t)idxs[i] * DIM;
            float a0 = 0, a1 = 0, a2 = 0, a3 = 0;
            for (int d = 0; d < DIM; d += 4) {
                float4 a = *(const float4*)(xq + d), v = *(const float4*)(xj + d);
                a0 += a.x * v.x; a1 += a.y * v.y; a2 += a.z * v.z; a3 += a.w * v.w;
            }
            se[i] = (a0 + a1) + (a2 + a3);
            mex = fmaxf(mex, se[i]);
        }
        float wgt[16], denom = 0.0f;
        for (int i = 0; i < n2; ++i) { wgt[i] = expf(se[i] - mex); denom += wgt[i]; }
        const float inv = 1.0f / denom;

        float* y = Y + ((size_t)b * NSEQ + q) * DIM;
        for (int d = 0; d < DIM; d += 4) {
            float ax = 0, ay = 0, az = 0, aw = 0;
            for (int i = 0; i < n2; ++i) {
                float4 v = *(const float4*)(Xf + (size_t)idxs[i] * DIM + d);
                ax += wgt[i] * v.x; ay += wgt[i] * v.y; az += wgt[i] * v.z; aw += wgt[i] * v.w;
            }
            float4 o; o.x = ax * inv; o.y = ay * inv; o.z = az * inv; o.w = aw * inv;
            *(float4*)(y + d) = o;
        }
    }
}

extern "C" void kernel_launch(void* const* d_in, const int* in_sizes, int n_in,
                              void* d_out, int out_size)
{
    const float* X = (const float*)d_in[0];
    float*       Y = (float*)d_out;
    cudaFuncSetAttribute(attn_mma_kernel,
                         cudaFuncAttributeMaxDynamicSharedMemorySize, SMEM_BYTES);
    cvt_kernel<<<(NB * NSEQ * DIM) / (256 * 4), 256>>>(X);
    attn_mma_kernel<<<NB * (NSEQ / BQ), NTHR, SMEM_BYTES>>>(X, Y);
}